// round 2
// baseline (speedup 1.0000x reference)
#include <cuda_runtime.h>

#define HIDDEN 4096
#define BATCH  4096
#define RANK   4

// Scratch for hq = h @ q_vec  [BATCH, RANK]  (no cudaMalloc allowed)
__device__ float g_hq[BATCH * RANK];

// ---------------------------------------------------------------------------
// Kernel 1: hq[i, r] = sum_j h[i, j] * q[j, r]      (memory-bound, ~15us)
// One block per row, 256 threads.
// ---------------------------------------------------------------------------
__global__ void __launch_bounds__(256) hq_kernel(const float* __restrict__ h,
                                                 const float* __restrict__ q)
{
    const int row = blockIdx.x;
    const int tid = threadIdx.x;
    const float* hrow = h + (size_t)row * HIDDEN;

    float a0 = 0.f, a1 = 0.f, a2 = 0.f, a3 = 0.f;
    for (int j = tid; j < HIDDEN; j += 256) {
        float hv = hrow[j];
        float4 qv = *reinterpret_cast<const float4*>(q + (size_t)j * 4);
        a0 += hv * qv.x;
        a1 += hv * qv.y;
        a2 += hv * qv.z;
        a3 += hv * qv.w;
    }
    // warp reduce
    #pragma unroll
    for (int off = 16; off > 0; off >>= 1) {
        a0 += __shfl_down_sync(0xffffffffu, a0, off);
        a1 += __shfl_down_sync(0xffffffffu, a1, off);
        a2 += __shfl_down_sync(0xffffffffu, a2, off);
        a3 += __shfl_down_sync(0xffffffffu, a3, off);
    }
    __shared__ float red[8][4];
    const int wid = tid >> 5, lid = tid & 31;
    if (lid == 0) {
        red[wid][0] = a0; red[wid][1] = a1; red[wid][2] = a2; red[wid][3] = a3;
    }
    __syncthreads();
    if (tid < 4) {
        float s = 0.f;
        #pragma unroll
        for (int w = 0; w < 8; w++) s += red[w][tid];
        g_hq[(size_t)row * 4 + tid] = s;
    }
}

// ---------------------------------------------------------------------------
// Kernel 2: fused SGEMM + epilogue
//   out[i,j] = h[i,j]*(1 + a[j]) + sum_r hq[i,r]*p[j,r] + sum_k x[i,k]*b[k,j]
// BM=BN=128, BK=16, 256 threads, 8x8 accumulators/thread.
// ---------------------------------------------------------------------------
#define BM 128
#define BN 128
#define BK 16
#define TM 8
#define TN 8
#define APAD 4   // pad so transposed stores are conflict-free

__global__ void __launch_bounds__(256) gemm_fused_kernel(
    const float* __restrict__ X,    // [B, K]   (x)
    const float* __restrict__ Bm,   // [K, N]   (b_mat)
    const float* __restrict__ H,    // [B, N]   (h)
    const float* __restrict__ Ad,   // [N]      (a_diag)
    const float* __restrict__ P,    // [N, 4]   (p_vec)
    float* __restrict__ Out)        // [B, N]
{
    __shared__ float As[BK][BM + APAD];  // transposed A tile (k-major)
    __shared__ float Bs[BK][BN];

    const int bx = blockIdx.x;           // N-tile
    const int by = blockIdx.y;           // M-tile
    const int tid = threadIdx.x;
    const int tm = tid >> 4;             // 0..15
    const int tn = tid & 15;             // 0..15

    const int row0 = by * BM;
    const int col0 = bx * BN;

    float acc[TM][TN];
    #pragma unroll
    for (int i = 0; i < TM; i++)
        #pragma unroll
        for (int j = 0; j < TN; j++) acc[i][j] = 0.f;

    for (int kt = 0; kt < HIDDEN; kt += BK) {
        // --- load A tile (BM x BK) transposed into As, 2 float4 per thread ---
        #pragma unroll
        for (int i = 0; i < 2; i++) {
            int v  = tid + i * 256;            // 0..511
            int m  = v >> 2;                   // 0..127
            int kq = (v & 3) << 2;             // 0,4,8,12
            float4 f = *reinterpret_cast<const float4*>(
                X + (size_t)(row0 + m) * HIDDEN + kt + kq);
            As[kq + 0][m] = f.x;
            As[kq + 1][m] = f.y;
            As[kq + 2][m] = f.z;
            As[kq + 3][m] = f.w;
        }
        // --- load B tile (BK x BN), 2 float4 per thread, coalesced ---
        #pragma unroll
        for (int i = 0; i < 2; i++) {
            int v = tid + i * 256;             // 0..511
            int k = v >> 5;                    // 0..15
            int n = (v & 31) << 2;             // 0..124
            *reinterpret_cast<float4*>(&Bs[k][n]) =
                *reinterpret_cast<const float4*>(
                    Bm + (size_t)(kt + k) * HIDDEN + col0 + n);
        }
        __syncthreads();

        #pragma unroll
        for (int k = 0; k < BK; k++) {
            float af[TM], bf[TN];
            float4 a0 = *reinterpret_cast<const float4*>(&As[k][tm * TM + 0]);
            float4 a1 = *reinterpret_cast<const float4*>(&As[k][tm * TM + 4]);
            float4 b0 = *reinterpret_cast<const float4*>(&Bs[k][tn * TN + 0]);
            float4 b1 = *reinterpret_cast<const float4*>(&Bs[k][tn * TN + 4]);
            af[0]=a0.x; af[1]=a0.y; af[2]=a0.z; af[3]=a0.w;
            af[4]=a1.x; af[5]=a1.y; af[6]=a1.z; af[7]=a1.w;
            bf[0]=b0.x; bf[1]=b0.y; bf[2]=b0.z; bf[3]=b0.w;
            bf[4]=b1.x; bf[5]=b1.y; bf[6]=b1.z; bf[7]=b1.w;
            #pragma unroll
            for (int i = 0; i < TM; i++)
                #pragma unroll
                for (int j = 0; j < TN; j++)
                    acc[i][j] = fmaf(af[i], bf[j], acc[i][j]);
        }
        __syncthreads();
    }

    // ------------------- epilogue: diag + rank-4 + store -------------------
    // per-column factors for this thread's 8 columns
    float colScale[TN];   // 1 + a[j]
    float pj[TN][4];
    #pragma unroll
    for (int j = 0; j < TN; j++) {
        int gcol = col0 + tn * TN + j;
        colScale[j] = 1.0f + Ad[gcol];
        float4 pv = *reinterpret_cast<const float4*>(P + (size_t)gcol * 4);
        pj[j][0] = pv.x; pj[j][1] = pv.y; pj[j][2] = pv.z; pj[j][3] = pv.w;
    }

    #pragma unroll
    for (int i = 0; i < TM; i++) {
        int grow = row0 + tm * TM + i;
        float4 hq = *reinterpret_cast<const float4*>(&g_hq[(size_t)grow * 4]);
        const float* hrow = H + (size_t)grow * HIDDEN + col0 + tn * TN;
        float* orow = Out + (size_t)grow * HIDDEN + col0 + tn * TN;

        float4 h0 = *reinterpret_cast<const float4*>(hrow + 0);
        float4 h1 = *reinterpret_cast<const float4*>(hrow + 4);
        float hv[TN] = {h0.x, h0.y, h0.z, h0.w, h1.x, h1.y, h1.z, h1.w};

        float res[TN];
        #pragma unroll
        for (int j = 0; j < TN; j++) {
            float r = acc[i][j];
            r = fmaf(hv[j], colScale[j], r);
            r = fmaf(hq.x, pj[j][0], r);
            r = fmaf(hq.y, pj[j][1], r);
            r = fmaf(hq.z, pj[j][2], r);
            r = fmaf(hq.w, pj[j][3], r);
            res[j] = r;
        }
        float4 o0 = {res[0], res[1], res[2], res[3]};
        float4 o1 = {res[4], res[5], res[6], res[7]};
        *reinterpret_cast<float4*>(orow + 0) = o0;
        *reinterpret_cast<float4*>(orow + 4) = o1;
    }
}

// ---------------------------------------------------------------------------
// Launch
// Inputs (metadata order): h, x, a_diag, p_vec, q_vec, b_mat
// ---------------------------------------------------------------------------
extern "C" void kernel_launch(void* const* d_in, const int* in_sizes, int n_in,
                              void* d_out, int out_size)
{
    const float* h      = (const float*)d_in[0];
    const float* x      = (const float*)d_in[1];
    const float* a_diag = (const float*)d_in[2];
    const float* p_vec  = (const float*)d_in[3];
    const float* q_vec  = (const float*)d_in[4];
    const float* b_mat  = (const float*)d_in[5];
    float* out = (float*)d_out;

    hq_kernel<<<BATCH, 256>>>(h, q_vec);

    dim3 grid(HIDDEN / BN, BATCH / BM);
    gemm_fused_kernel<<<grid, 256>>>(x, b_mat, h, a_diag, p_vec, out);
}

// round 3
// speedup vs baseline: 1.0004x; 1.0004x over previous
#include <cuda_runtime.h>

#define HIDDEN 4096
#define BATCH  4096
#define RANK   4

// Scratch for hq = h @ q_vec  [BATCH, RANK]  (no cudaMalloc allowed)
__device__ float g_hq[BATCH * RANK];

// ---------------------------------------------------------------------------
// Kernel 1: hq[i, r] = sum_j h[i, j] * q[j, r]      (memory-bound, ~15us)
// One block per row, 256 threads.
// ---------------------------------------------------------------------------
__global__ void __launch_bounds__(256) hq_kernel(const float* __restrict__ h,
                                                 const float* __restrict__ q)
{
    const int row = blockIdx.x;
    const int tid = threadIdx.x;
    const float* hrow = h + (size_t)row * HIDDEN;

    float a0 = 0.f, a1 = 0.f, a2 = 0.f, a3 = 0.f;
    for (int j = tid; j < HIDDEN; j += 256) {
        float hv = hrow[j];
        float4 qv = *reinterpret_cast<const float4*>(q + (size_t)j * 4);
        a0 += hv * qv.x;
        a1 += hv * qv.y;
        a2 += hv * qv.z;
        a3 += hv * qv.w;
    }
    // warp reduce
    #pragma unroll
    for (int off = 16; off > 0; off >>= 1) {
        a0 += __shfl_down_sync(0xffffffffu, a0, off);
        a1 += __shfl_down_sync(0xffffffffu, a1, off);
        a2 += __shfl_down_sync(0xffffffffu, a2, off);
        a3 += __shfl_down_sync(0xffffffffu, a3, off);
    }
    __shared__ float red[8][4];
    const int wid = tid >> 5, lid = tid & 31;
    if (lid == 0) {
        red[wid][0] = a0; red[wid][1] = a1; red[wid][2] = a2; red[wid][3] = a3;
    }
    __syncthreads();
    if (tid < 4) {
        float s = 0.f;
        #pragma unroll
        for (int w = 0; w < 8; w++) s += red[w][tid];
        g_hq[(size_t)row * 4 + tid] = s;
    }
}

// ---------------------------------------------------------------------------
// Kernel 2: fused SGEMM + epilogue
//   out[i,j] = h[i,j]*(1 + a[j]) + sum_r hq[i,r]*p[j,r] + sum_k x[i,k]*b[k,j]
// BM=BN=128, BK=16, 256 threads, 8x8 accumulators/thread.
// ---------------------------------------------------------------------------
#define BM 128
#define BN 128
#define BK 16
#define TM 8
#define TN 8
#define APAD 4   // pad so transposed stores are conflict-free

__global__ void __launch_bounds__(256) gemm_fused_kernel(
    const float* __restrict__ X,    // [B, K]   (x)
    const float* __restrict__ Bm,   // [K, N]   (b_mat)
    const float* __restrict__ H,    // [B, N]   (h)
    const float* __restrict__ Ad,   // [N]      (a_diag)
    const float* __restrict__ P,    // [N, 4]   (p_vec)
    float* __restrict__ Out)        // [B, N]
{
    __shared__ float As[BK][BM + APAD];  // transposed A tile (k-major)
    __shared__ float Bs[BK][BN];

    const int bx = blockIdx.x;           // N-tile
    const int by = blockIdx.y;           // M-tile
    const int tid = threadIdx.x;
    const int tm = tid >> 4;             // 0..15
    const int tn = tid & 15;             // 0..15

    const int row0 = by * BM;
    const int col0 = bx * BN;

    float acc[TM][TN];
    #pragma unroll
    for (int i = 0; i < TM; i++)
        #pragma unroll
        for (int j = 0; j < TN; j++) acc[i][j] = 0.f;

    for (int kt = 0; kt < HIDDEN; kt += BK) {
        // --- load A tile (BM x BK) transposed into As, 2 float4 per thread ---
        #pragma unroll
        for (int i = 0; i < 2; i++) {
            int v  = tid + i * 256;            // 0..511
            int m  = v >> 2;                   // 0..127
            int kq = (v & 3) << 2;             // 0,4,8,12
            float4 f = *reinterpret_cast<const float4*>(
                X + (size_t)(row0 + m) * HIDDEN + kt + kq);
            As[kq + 0][m] = f.x;
            As[kq + 1][m] = f.y;
            As[kq + 2][m] = f.z;
            As[kq + 3][m] = f.w;
        }
        // --- load B tile (BK x BN), 2 float4 per thread, coalesced ---
        #pragma unroll
        for (int i = 0; i < 2; i++) {
            int v = tid + i * 256;             // 0..511
            int k = v >> 5;                    // 0..15
            int n = (v & 31) << 2;             // 0..124
            *reinterpret_cast<float4*>(&Bs[k][n]) =
                *reinterpret_cast<const float4*>(
                    Bm + (size_t)(kt + k) * HIDDEN + col0 + n);
        }
        __syncthreads();

        #pragma unroll
        for (int k = 0; k < BK; k++) {
            float af[TM], bf[TN];
            float4 a0 = *reinterpret_cast<const float4*>(&As[k][tm * TM + 0]);
            float4 a1 = *reinterpret_cast<const float4*>(&As[k][tm * TM + 4]);
            float4 b0 = *reinterpret_cast<const float4*>(&Bs[k][tn * TN + 0]);
            float4 b1 = *reinterpret_cast<const float4*>(&Bs[k][tn * TN + 4]);
            af[0]=a0.x; af[1]=a0.y; af[2]=a0.z; af[3]=a0.w;
            af[4]=a1.x; af[5]=a1.y; af[6]=a1.z; af[7]=a1.w;
            bf[0]=b0.x; bf[1]=b0.y; bf[2]=b0.z; bf[3]=b0.w;
            bf[4]=b1.x; bf[5]=b1.y; bf[6]=b1.z; bf[7]=b1.w;
            #pragma unroll
            for (int i = 0; i < TM; i++)
                #pragma unroll
                for (int j = 0; j < TN; j++)
                    acc[i][j] = fmaf(af[i], bf[j], acc[i][j]);
        }
        __syncthreads();
    }

    // ------------------- epilogue: diag + rank-4 + store -------------------
    // per-column factors for this thread's 8 columns
    float colScale[TN];   // 1 + a[j]
    float pj[TN][4];
    #pragma unroll
    for (int j = 0; j < TN; j++) {
        int gcol = col0 + tn * TN + j;
        colScale[j] = 1.0f + Ad[gcol];
        float4 pv = *reinterpret_cast<const float4*>(P + (size_t)gcol * 4);
        pj[j][0] = pv.x; pj[j][1] = pv.y; pj[j][2] = pv.z; pj[j][3] = pv.w;
    }

    #pragma unroll
    for (int i = 0; i < TM; i++) {
        int grow = row0 + tm * TM + i;
        float4 hq = *reinterpret_cast<const float4*>(&g_hq[(size_t)grow * 4]);
        const float* hrow = H + (size_t)grow * HIDDEN + col0 + tn * TN;
        float* orow = Out + (size_t)grow * HIDDEN + col0 + tn * TN;

        float4 h0 = *reinterpret_cast<const float4*>(hrow + 0);
        float4 h1 = *reinterpret_cast<const float4*>(hrow + 4);
        float hv[TN] = {h0.x, h0.y, h0.z, h0.w, h1.x, h1.y, h1.z, h1.w};

        float res[TN];
        #pragma unroll
        for (int j = 0; j < TN; j++) {
            float r = acc[i][j];
            r = fmaf(hv[j], colScale[j], r);
            r = fmaf(hq.x, pj[j][0], r);
            r = fmaf(hq.y, pj[j][1], r);
            r = fmaf(hq.z, pj[j][2], r);
            r = fmaf(hq.w, pj[j][3], r);
            res[j] = r;
        }
        float4 o0 = {res[0], res[1], res[2], res[3]};
        float4 o1 = {res[4], res[5], res[6], res[7]};
        *reinterpret_cast<float4*>(orow + 0) = o0;
        *reinterpret_cast<float4*>(orow + 4) = o1;
    }
}

// ---------------------------------------------------------------------------
// Launch
// Inputs (metadata order): h, x, a_diag, p_vec, q_vec, b_mat
// ---------------------------------------------------------------------------
extern "C" void kernel_launch(void* const* d_in, const int* in_sizes, int n_in,
                              void* d_out, int out_size)
{
    const float* h      = (const float*)d_in[0];
    const float* x      = (const float*)d_in[1];
    const float* a_diag = (const float*)d_in[2];
    const float* p_vec  = (const float*)d_in[3];
    const float* q_vec  = (const float*)d_in[4];
    const float* b_mat  = (const float*)d_in[5];
    float* out = (float*)d_out;

    hq_kernel<<<BATCH, 256>>>(h, q_vec);

    dim3 grid(HIDDEN / BN, BATCH / BM);
    gemm_fused_kernel<<<grid, 256>>>(x, b_mat, h, a_diag, p_vec, out);
}